// round 16
// baseline (speedup 1.0000x reference)
#include <cuda_runtime.h>

#define ND 50000
#define NP 50000
#define NN 50000      // ND == NP
#define EE 600000
#define DIN 128
#define DH  128
#define DO  64

// ---------------- float scratch ----------------
constexpr size_t H_D    = 0;
constexpr size_t H_P    = H_D    + (size_t)ND * DH;
constexpr size_t T1_DDI = H_P    + (size_t)NP * DH;
constexpr size_t T1_DPI = T1_DDI + (size_t)ND * DH;
constexpr size_t T1_PPI = T1_DPI + (size_t)ND * DH;
constexpr size_t T2_DDI = T1_PPI + (size_t)NP * DH;
constexpr size_t T2_DPI = T2_DDI + (size_t)ND * DO;
constexpr size_t T2_PPI = T2_DPI + (size_t)ND * DO;
constexpr size_t FTOTAL = T2_PPI + (size_t)NP * DO;

__device__ float g_buf[FTOTAL];

// ---------------- int scratch (CSR) ----------------
constexpr size_t DEG0 = 0;
constexpr size_t OFF0 = DEG0 + 3 * (size_t)NN;
constexpr size_t CUR0 = OFF0 + 3 * (size_t)NN;
constexpr size_t CSR0 = CUR0 + 3 * (size_t)NN;
constexpr size_t ITOTAL = CSR0 + 3 * (size_t)EE;

__device__ int g_ibuf[ITOTAL];

// ---------------- CSR build ----------------

__global__ void zero_int_kernel(int* __restrict__ p, int n) {
    int i = blockIdx.x * blockDim.x + threadIdx.x;
    int stride = gridDim.x * blockDim.x;
    for (; i < n; i += stride) p[i] = 0;
}

__global__ void degree_kernel(const int* __restrict__ dst_ddi,
                              const int* __restrict__ dst_dpi,
                              const int* __restrict__ dst_ppi,
                              int* __restrict__ deg_ddi,
                              int* __restrict__ deg_dpi,
                              int* __restrict__ deg_ppi) {
    int i = blockIdx.x * blockDim.x + threadIdx.x;
    if (i < EE) {
        atomicAdd(&deg_ddi[dst_ddi[i]], 1);
        atomicAdd(&deg_dpi[dst_dpi[i]], 1);
        atomicAdd(&deg_ppi[dst_ppi[i]], 1);
    }
}

__global__ void __launch_bounds__(1024) scan3_kernel(int* __restrict__ ibuf) {
    const int* deg = ibuf + DEG0 + (size_t)blockIdx.x * NN;
    int* off = ibuf + OFF0 + (size_t)blockIdx.x * NN;
    int* cur = ibuf + CUR0 + (size_t)blockIdx.x * NN;

    __shared__ int warp_tot[32];
    __shared__ int carry_sh;
    int t = threadIdx.x;
    int lane = t & 31;
    int wid  = t >> 5;
    if (t == 0) carry_sh = 0;
    __syncthreads();

    for (int base = 0; base < NN; base += 1024) {
        int x = (base + t < NN) ? deg[base + t] : 0;
        int v = x;
#pragma unroll
        for (int s = 1; s < 32; s <<= 1) {
            int y = __shfl_up_sync(0xffffffffu, v, s);
            if (lane >= s) v += y;
        }
        if (lane == 31) warp_tot[wid] = v;
        __syncthreads();
        if (wid == 0) {
            int w = warp_tot[lane];
#pragma unroll
            for (int s = 1; s < 32; s <<= 1) {
                int y = __shfl_up_sync(0xffffffffu, w, s);
                if (lane >= s) w += y;
            }
            warp_tot[lane] = w;
        }
        __syncthreads();
        int warp_off = (wid == 0) ? 0 : warp_tot[wid - 1];
        int excl = v - x + warp_off;
        int c = carry_sh;
        if (base + t < NN) {
            off[base + t] = c + excl;
            cur[base + t] = c + excl;
        }
        int tile_tot = warp_tot[31];
        __syncthreads();
        if (t == 0) carry_sh = c + tile_tot;
        __syncthreads();
    }
}

__global__ void fill_csr3_kernel(const int* __restrict__ s0, const int* __restrict__ d0,
                                 int* __restrict__ c0, int* __restrict__ r0,
                                 const int* __restrict__ s1, const int* __restrict__ d1,
                                 int* __restrict__ c1, int* __restrict__ r1,
                                 const int* __restrict__ s2, const int* __restrict__ d2,
                                 int* __restrict__ c2, int* __restrict__ r2) {
    int i = blockIdx.x * blockDim.x + threadIdx.x;
    if (i < EE) {
        int p = atomicAdd(&c0[d0[i]], 1);
        r0[p] = s0[i];
    } else if (i < 2 * EE) {
        int j = i - EE;
        int p = atomicAdd(&c1[d1[j]], 1);
        r1[p] = s1[j];
    } else if (i < 3 * EE) {
        int j = i - 2 * EE;
        int p = atomicAdd(&c2[d2[j]], 1);
        r2[p] = s2[j];
    }
}

// ---------------- GEMM: low-register tiles for high occupancy ----------------
// BM=32, 256 threads. N=128: TM=4 (~45 regs, ~6 CTAs/SM). N=64: TM=2 (~32 regs, 8 CTAs/SM).

#define FMA4(accr, a, w0, w1, w2, w3)        \
    do {                                     \
        accr[0] += (a).x * (w0).x;           \
        accr[0] += (a).y * (w1).x;           \
        accr[0] += (a).z * (w2).x;           \
        accr[0] += (a).w * (w3).x;           \
        accr[1] += (a).x * (w0).y;           \
        accr[1] += (a).y * (w1).y;           \
        accr[1] += (a).z * (w2).y;           \
        accr[1] += (a).w * (w3).y;           \
        accr[2] += (a).x * (w0).z;           \
        accr[2] += (a).y * (w1).z;           \
        accr[2] += (a).z * (w2).z;           \
        accr[2] += (a).w * (w3).z;           \
        accr[3] += (a).x * (w0).w;           \
        accr[3] += (a).y * (w1).w;           \
        accr[3] += (a).z * (w2).w;           \
        accr[3] += (a).w * (w3).w;           \
    } while (0)

template <int N>
__global__ void __launch_bounds__(256) gemm32_kernel(const float* __restrict__ A,
                                                     const float* __restrict__ W,
                                                     float* __restrict__ C, int M) {
    constexpr int BM = 32;
    constexpr int K  = 128;
    constexpr int BK = 32;
    constexpr int NTX = N / 4;         // 32 (N=128) / 16 (N=64)
    constexpr int NTY = 256 / NTX;     // 8 / 16
    constexpr int TM  = BM / NTY;      // 4 / 2

    __shared__ float As[BM * K];       // 16 KB
    __shared__ float Ws[BK * N];       // 16 KB (N=128) / 8 KB (N=64)

    int tid = threadIdx.x;
    int m0  = blockIdx.x * BM;
    int rows = M - m0; if (rows > BM) rows = BM;

    const float4* A4 = (const float4*)(A + (size_t)m0 * K);
    for (int i = tid; i < rows * (K / 4); i += 256)
        ((float4*)As)[i] = A4[i];

    int tx = tid % NTX;
    int ty = tid / NTX;
    float acc[TM][4];
#pragma unroll
    for (int r = 0; r < TM; r++) { acc[r][0]=0.f; acc[r][1]=0.f; acc[r][2]=0.f; acc[r][3]=0.f; }

    const float4* As4 = (const float4*)As;
    const float4* Ws4 = (const float4*)Ws;

    for (int kk = 0; kk < K; kk += BK) {
        __syncthreads();
        const float4* W4 = (const float4*)(W + (size_t)kk * N);
        for (int i = tid; i < BK * N / 4; i += 256)
            ((float4*)Ws)[i] = W4[i];
        __syncthreads();
#pragma unroll
        for (int k4 = 0; k4 < BK / 4; k4++) {
            float4 w0 = Ws4[(k4 * 4 + 0) * (N / 4) + tx];
            float4 w1 = Ws4[(k4 * 4 + 1) * (N / 4) + tx];
            float4 w2 = Ws4[(k4 * 4 + 2) * (N / 4) + tx];
            float4 w3 = Ws4[(k4 * 4 + 3) * (N / 4) + tx];
#pragma unroll
            for (int r = 0; r < TM; r++) {
                float4 a = As4[(ty * TM + r) * (K / 4) + (kk / 4) + k4];
                FMA4(acc[r], a, w0, w1, w2, w3);
            }
        }
    }

#pragma unroll
    for (int r = 0; r < TM; r++) {
        int m = m0 + ty * TM + r;
        if (m < M) {
            ((float4*)(C + (size_t)m * N))[tx] =
                make_float4(acc[r][0], acc[r][1], acc[r][2], acc[r][3]);
        }
    }
}

// ---- gather aggregation (exact R7 versions — measured at 406us baseline) ----

__global__ void __launch_bounds__(256) agg128_kernel(const float* __restrict__ t,
                                                     const int* __restrict__ csr,
                                                     const int* __restrict__ off,
                                                     const int* __restrict__ deg,
                                                     const float* __restrict__ b,
                                                     float* __restrict__ out, int n) {
    int gw   = (blockIdx.x * blockDim.x + threadIdx.x) >> 5;
    int lane = threadIdx.x & 31;
    if (gw >= n) return;
    int o  = __ldg(&off[gw]);
    int dg = __ldg(&deg[gw]);
    int e  = o + dg;
    float4 acc = make_float4(0.f, 0.f, 0.f, 0.f);
    int i = o;
    for (; i + 3 < e; i += 4) {
        int s0 = __ldg(&csr[i]);
        int s1 = __ldg(&csr[i + 1]);
        int s2 = __ldg(&csr[i + 2]);
        int s3 = __ldg(&csr[i + 3]);
        float4 v0 = __ldg((const float4*)(t + (size_t)s0 * 128) + lane);
        float4 v1 = __ldg((const float4*)(t + (size_t)s1 * 128) + lane);
        float4 v2 = __ldg((const float4*)(t + (size_t)s2 * 128) + lane);
        float4 v3 = __ldg((const float4*)(t + (size_t)s3 * 128) + lane);
        acc.x += (v0.x + v1.x) + (v2.x + v3.x);
        acc.y += (v0.y + v1.y) + (v2.y + v3.y);
        acc.z += (v0.z + v1.z) + (v2.z + v3.z);
        acc.w += (v0.w + v1.w) + (v2.w + v3.w);
    }
    for (; i < e; i++) {
        int s = __ldg(&csr[i]);
        float4 v = __ldg((const float4*)(t + (size_t)s * 128) + lane);
        acc.x += v.x; acc.y += v.y; acc.z += v.z; acc.w += v.w;
    }
    float inv = 1.0f / fmaxf((float)dg, 1.0f);
    float4 bb = __ldg((const float4*)b + lane);
    ((float4*)(out + (size_t)gw * 128))[lane] =
        make_float4(acc.x * inv + bb.x, acc.y * inv + bb.y,
                    acc.z * inv + bb.z, acc.w * inv + bb.w);
}

__global__ void __launch_bounds__(256) agg128_dual_kernel(
        const float* __restrict__ tA, const int* __restrict__ csrA,
        const int* __restrict__ offA, const int* __restrict__ degA,
        const float* __restrict__ bA,
        const float* __restrict__ tB, const int* __restrict__ csrB,
        const int* __restrict__ offB, const int* __restrict__ degB,
        const float* __restrict__ bB,
        float* __restrict__ out, int n) {
    int gw   = (blockIdx.x * blockDim.x + threadIdx.x) >> 5;
    int lane = threadIdx.x & 31;
    if (gw >= n) return;

    int dgA = __ldg(&degA[gw]);
    int dgB = __ldg(&degB[gw]);

    float4 accA = make_float4(0.f, 0.f, 0.f, 0.f);
    {
        int o = __ldg(&offA[gw]); int e = o + dgA;
        int i = o;
        for (; i + 3 < e; i += 4) {
            int s0 = __ldg(&csrA[i]);
            int s1 = __ldg(&csrA[i + 1]);
            int s2 = __ldg(&csrA[i + 2]);
            int s3 = __ldg(&csrA[i + 3]);
            float4 v0 = __ldg((const float4*)(tA + (size_t)s0 * 128) + lane);
            float4 v1 = __ldg((const float4*)(tA + (size_t)s1 * 128) + lane);
            float4 v2 = __ldg((const float4*)(tA + (size_t)s2 * 128) + lane);
            float4 v3 = __ldg((const float4*)(tA + (size_t)s3 * 128) + lane);
            accA.x += (v0.x + v1.x) + (v2.x + v3.x);
            accA.y += (v0.y + v1.y) + (v2.y + v3.y);
            accA.z += (v0.z + v1.z) + (v2.z + v3.z);
            accA.w += (v0.w + v1.w) + (v2.w + v3.w);
        }
        for (; i < e; i++) {
            int s = __ldg(&csrA[i]);
            float4 v = __ldg((const float4*)(tA + (size_t)s * 128) + lane);
            accA.x += v.x; accA.y += v.y; accA.z += v.z; accA.w += v.w;
        }
    }
    float4 accB = make_float4(0.f, 0.f, 0.f, 0.f);
    {
        int o = __ldg(&offB[gw]); int e = o + dgB;
        int i = o;
        for (; i + 3 < e; i += 4) {
            int s0 = __ldg(&csrB[i]);
            int s1 = __ldg(&csrB[i + 1]);
            int s2 = __ldg(&csrB[i + 2]);
            int s3 = __ldg(&csrB[i + 3]);
            float4 v0 = __ldg((const float4*)(tB + (size_t)s0 * 128) + lane);
            float4 v1 = __ldg((const float4*)(tB + (size_t)s1 * 128) + lane);
            float4 v2 = __ldg((const float4*)(tB + (size_t)s2 * 128) + lane);
            float4 v3 = __ldg((const float4*)(tB + (size_t)s3 * 128) + lane);
            accB.x += (v0.x + v1.x) + (v2.x + v3.x);
            accB.y += (v0.y + v1.y) + (v2.y + v3.y);
            accB.z += (v0.z + v1.z) + (v2.z + v3.z);
            accB.w += (v0.w + v1.w) + (v2.w + v3.w);
        }
        for (; i < e; i++) {
            int s = __ldg(&csrB[i]);
            float4 v = __ldg((const float4*)(tB + (size_t)s * 128) + lane);
            accB.x += v.x; accB.y += v.y; accB.z += v.z; accB.w += v.w;
        }
    }
    float invA = 1.0f / fmaxf((float)dgA, 1.0f);
    float invB = 1.0f / fmaxf((float)dgB, 1.0f);
    float4 bbA = __ldg((const float4*)bA + lane);
    float4 bbB = __ldg((const float4*)bB + lane);
    ((float4*)(out + (size_t)gw * 128))[lane] =
        make_float4(accA.x * invA + bbA.x + accB.x * invB + bbB.x,
                    accA.y * invA + bbA.y + accB.y * invB + bbB.y,
                    accA.z * invA + bbA.z + accB.z * invB + bbB.z,
                    accA.w * invA + bbA.w + accB.w * invB + bbB.w);
}

__global__ void __launch_bounds__(256) agg64_kernel(const float* __restrict__ t,
                                                    const int* __restrict__ csr,
                                                    const int* __restrict__ off,
                                                    const int* __restrict__ deg,
                                                    const float* __restrict__ b,
                                                    float* __restrict__ out, int n) {
    int gw   = (blockIdx.x * blockDim.x + threadIdx.x) >> 5;
    int lane = threadIdx.x & 31;
    if (gw >= n) return;
    int half = lane >> 4;
    int sub  = lane & 15;
    int o  = __ldg(&off[gw]);
    int dg = __ldg(&deg[gw]);
    int e  = o + dg;
    float4 acc = make_float4(0.f, 0.f, 0.f, 0.f);
    int i = o;
    for (; i + 3 < e; i += 4) {
        int s0 = __ldg(&csr[i + half]);
        int s1 = __ldg(&csr[i + 2 + half]);
        float4 v0 = __ldg((const float4*)(t + (size_t)s0 * 64) + sub);
        float4 v1 = __ldg((const float4*)(t + (size_t)s1 * 64) + sub);
        acc.x += v0.x + v1.x; acc.y += v0.y + v1.y;
        acc.z += v0.z + v1.z; acc.w += v0.w + v1.w;
    }
    for (; i + 1 < e; i += 2) {
        int s = __ldg(&csr[i + half]);
        float4 v = __ldg((const float4*)(t + (size_t)s * 64) + sub);
        acc.x += v.x; acc.y += v.y; acc.z += v.z; acc.w += v.w;
    }
    if (i < e && half == 0) {
        int s = __ldg(&csr[i]);
        float4 v = __ldg((const float4*)(t + (size_t)s * 64) + sub);
        acc.x += v.x; acc.y += v.y; acc.z += v.z; acc.w += v.w;
    }
    acc.x += __shfl_xor_sync(0xffffffffu, acc.x, 16);
    acc.y += __shfl_xor_sync(0xffffffffu, acc.y, 16);
    acc.z += __shfl_xor_sync(0xffffffffu, acc.z, 16);
    acc.w += __shfl_xor_sync(0xffffffffu, acc.w, 16);
    if (half == 0) {
        float inv = 1.0f / fmaxf((float)dg, 1.0f);
        float4 bb = __ldg((const float4*)b + sub);
        ((float4*)(out + (size_t)gw * 64))[sub] =
            make_float4(acc.x * inv + bb.x, acc.y * inv + bb.y,
                        acc.z * inv + bb.z, acc.w * inv + bb.w);
    }
}

__global__ void __launch_bounds__(256) agg64_dual_kernel(
        const float* __restrict__ tA, const int* __restrict__ csrA,
        const int* __restrict__ offA, const int* __restrict__ degA,
        const float* __restrict__ bA,
        const float* __restrict__ tB, const int* __restrict__ csrB,
        const int* __restrict__ offB, const int* __restrict__ degB,
        const float* __restrict__ bB,
        float* __restrict__ out, int n) {
    int gw   = (blockIdx.x * blockDim.x + threadIdx.x) >> 5;
    int lane = threadIdx.x & 31;
    if (gw >= n) return;
    int half = lane >> 4;
    int sub  = lane & 15;

    int dgA = __ldg(&degA[gw]);
    int dgB = __ldg(&degB[gw]);

    float4 accA = make_float4(0.f, 0.f, 0.f, 0.f);
    {
        int o = __ldg(&offA[gw]); int e = o + dgA;
        int i = o;
        for (; i + 3 < e; i += 4) {
            int s0 = __ldg(&csrA[i + half]);
            int s1 = __ldg(&csrA[i + 2 + half]);
            float4 v0 = __ldg((const float4*)(tA + (size_t)s0 * 64) + sub);
            float4 v1 = __ldg((const float4*)(tA + (size_t)s1 * 64) + sub);
            accA.x += v0.x + v1.x; accA.y += v0.y + v1.y;
            accA.z += v0.z + v1.z; accA.w += v0.w + v1.w;
        }
        for (; i + 1 < e; i += 2) {
            int s = __ldg(&csrA[i + half]);
            float4 v = __ldg((const float4*)(tA + (size_t)s * 64) + sub);
            accA.x += v.x; accA.y += v.y; accA.z += v.z; accA.w += v.w;
        }
        if (i < e && half == 0) {
            int s = __ldg(&csrA[i]);
            float4 v = __ldg((const float4*)(tA + (size_t)s * 64) + sub);
            accA.x += v.x; accA.y += v.y; accA.z += v.z; accA.w += v.w;
        }
    }
    float4 accB = make_float4(0.f, 0.f, 0.f, 0.f);
    {
        int o = __ldg(&offB[gw]); int e = o + dgB;
        int i = o;
        for (; i + 3 < e; i += 4) {
            int s0 = __ldg(&csrB[i + half]);
            int s1 = __ldg(&csrB[i + 2 + half]);
            float4 v0 = __ldg((const float4*)(tB + (size_t)s0 * 64) + sub);
            float4 v1 = __ldg((const float4*)(tB + (size_t)s1 * 64) + sub);
            accB.x += v0.x + v1.x; accB.y += v0.y + v1.y;
            accB.z += v0.z + v1.z; accB.w += v0.w + v1.w;
        }
        for (; i + 1 < e; i += 2) {
            int s = __ldg(&csrB[i + half]);
            float4 v = __ldg((const float4*)(tB + (size_t)s * 64) + sub);
            accB.x += v.x; accB.y += v.y; accB.z += v.z; accB.w += v.w;
        }
        if (i < e && half == 0) {
            int s = __ldg(&csrB[i]);
            float4 v = __ldg((const float4*)(tB + (size_t)s * 64) + sub);
            accB.x += v.x; accB.y += v.y; accB.z += v.z; accB.w += v.w;
        }
    }
    accA.x += __shfl_xor_sync(0xffffffffu, accA.x, 16);
    accA.y += __shfl_xor_sync(0xffffffffu, accA.y, 16);
    accA.z += __shfl_xor_sync(0xffffffffu, accA.z, 16);
    accA.w += __shfl_xor_sync(0xffffffffu, accA.w, 16);
    accB.x += __shfl_xor_sync(0xffffffffu, accB.x, 16);
    accB.y += __shfl_xor_sync(0xffffffffu, accB.y, 16);
    accB.z += __shfl_xor_sync(0xffffffffu, accB.z, 16);
    accB.w += __shfl_xor_sync(0xffffffffu, accB.w, 16);
    if (half == 0) {
        float invA = 1.0f / fmaxf((float)dgA, 1.0f);
        float invB = 1.0f / fmaxf((float)dgB, 1.0f);
        float4 bbA = __ldg((const float4*)bA + sub);
        float4 bbB = __ldg((const float4*)bB + sub);
        ((float4*)(out + (size_t)gw * 64))[sub] =
            make_float4(accA.x * invA + bbA.x + accB.x * invB + bbB.x,
                        accA.y * invA + bbA.y + accB.y * invB + bbB.y,
                        accA.z * invA + bbA.z + accB.z * invB + bbB.z,
                        accA.w * invA + bbA.w + accB.w * invB + bbB.w);
    }
}

// ---------------- launch ----------------

extern "C" void kernel_launch(void* const* d_in, const int* in_sizes, int n_in,
                              void* d_out, int out_size) {
    const float* x_drug = (const float*)d_in[0];
    const float* x_prot = (const float*)d_in[1];
    const int* src_ddi  = (const int*)d_in[2];
    const int* dst_ddi  = (const int*)d_in[3];
    const int* src_dpi  = (const int*)d_in[4];
    const int* dst_dpi  = (const int*)d_in[5];
    const int* src_ppi  = (const int*)d_in[6];
    const int* dst_ppi  = (const int*)d_in[7];
    const float* W1_ddi = (const float*)d_in[8];
    const float* b1_ddi = (const float*)d_in[9];
    const float* W1_dpi = (const float*)d_in[10];
    const float* b1_dpi = (const float*)d_in[11];
    const float* W1_ppi = (const float*)d_in[12];
    const float* b1_ppi = (const float*)d_in[13];
    const float* W2_ddi = (const float*)d_in[14];
    const float* b2_ddi = (const float*)d_in[15];
    const float* W2_dpi = (const float*)d_in[16];
    const float* b2_dpi = (const float*)d_in[17];
    const float* W2_ppi = (const float*)d_in[18];
    const float* b2_ppi = (const float*)d_in[19];
    float* out = (float*)d_out;

    float* B = nullptr;
    cudaGetSymbolAddress((void**)&B, g_buf);
    int* IB = nullptr;
    cudaGetSymbolAddress((void**)&IB, g_ibuf);

    float* h_d    = B + H_D;
    float* h_p    = B + H_P;
    float* t1_ddi = B + T1_DDI;
    float* t1_dpi = B + T1_DPI;
    float* t1_ppi = B + T1_PPI;
    float* t2_ddi = B + T2_DDI;
    float* t2_dpi = B + T2_DPI;
    float* t2_ppi = B + T2_PPI;

    int* deg_ddi = IB + DEG0;
    int* deg_dpi = IB + DEG0 + NN;
    int* deg_ppi = IB + DEG0 + 2 * NN;
    int* off_ddi = IB + OFF0;
    int* off_dpi = IB + OFF0 + NN;
    int* off_ppi = IB + OFF0 + 2 * NN;
    int* cur_ddi = IB + CUR0;
    int* cur_dpi = IB + CUR0 + NN;
    int* cur_ppi = IB + CUR0 + 2 * NN;
    int* csr_ddi = IB + CSR0;
    int* csr_dpi = IB + CSR0 + EE;
    int* csr_ppi = IB + CSR0 + 2 * EE;

    // ---- build CSR (3 relations) ----
    zero_int_kernel<<<64, 1024>>>(IB + DEG0, 3 * NN);
    degree_kernel<<<(EE + 255) / 256, 256>>>(dst_ddi, dst_dpi, dst_ppi,
                                             deg_ddi, deg_dpi, deg_ppi);
    scan3_kernel<<<3, 1024>>>(IB);
    fill_csr3_kernel<<<(3 * EE + 255) / 256, 256>>>(
        src_ddi, dst_ddi, cur_ddi, csr_ddi,
        src_dpi, dst_dpi, cur_dpi, csr_dpi,
        src_ppi, dst_ppi, cur_ppi, csr_ppi);

    // ---- layer 1 (high-occupancy single GEMMs) ----
    const int GB32 = (NN + 31) / 32;   // 1563
    gemm32_kernel<128><<<GB32, 256>>>(x_drug, W1_ddi, t1_ddi, ND);
    gemm32_kernel<128><<<GB32, 256>>>(x_drug, W1_dpi, t1_dpi, ND);
    gemm32_kernel<128><<<GB32, 256>>>(x_prot, W1_ppi, t1_ppi, NP);

    const int AB = (NN * 32 + 255) / 256;
    agg128_kernel<<<AB, 256>>>(t1_ddi, csr_ddi, off_ddi, deg_ddi, b1_ddi, h_d, ND);
    agg128_dual_kernel<<<AB, 256>>>(t1_dpi, csr_dpi, off_dpi, deg_dpi, b1_dpi,
                                    t1_ppi, csr_ppi, off_ppi, deg_ppi, b1_ppi,
                                    h_p, NP);

    // ---- layer 2 ----
    gemm32_kernel<64><<<GB32, 256>>>(h_d, W2_ddi, t2_ddi, ND);
    gemm32_kernel<64><<<GB32, 256>>>(h_d, W2_dpi, t2_dpi, ND);
    gemm32_kernel<64><<<GB32, 256>>>(h_p, W2_ppi, t2_ppi, NP);

    agg64_kernel<<<AB, 256>>>(t2_ddi, csr_ddi, off_ddi, deg_ddi, b2_ddi, out, ND);
    agg64_dual_kernel<<<AB, 256>>>(t2_dpi, csr_dpi, off_dpi, deg_dpi, b2_dpi,
                                   t2_ppi, csr_ppi, off_ppi, deg_ppi, b2_ppi,
                                   out + (size_t)ND * DO, NP);
}

// round 17
// speedup vs baseline: 1.1247x; 1.1247x over previous
#include <cuda_runtime.h>

#define ND 50000
#define NP 50000
#define NN 50000      // ND == NP
#define EE 600000
#define DIN 128
#define DH  128
#define DO  64

// ---------------- float scratch ----------------
constexpr size_t H_D    = 0;
constexpr size_t H_P    = H_D    + (size_t)ND * DH;
constexpr size_t T1_DDI = H_P    + (size_t)NP * DH;
constexpr size_t T1_DPI = T1_DDI + (size_t)ND * DH;
constexpr size_t T1_PPI = T1_DPI + (size_t)ND * DH;
constexpr size_t T2_DDI = T1_PPI + (size_t)NP * DH;
constexpr size_t T2_DPI = T2_DDI + (size_t)ND * DO;
constexpr size_t T2_PPI = T2_DPI + (size_t)ND * DO;
constexpr size_t FTOTAL = T2_PPI + (size_t)NP * DO;

__device__ float g_buf[FTOTAL];

// ---------------- int scratch (CSR) ----------------
constexpr size_t DEG0 = 0;
constexpr size_t OFF0 = DEG0 + 3 * (size_t)NN;
constexpr size_t CUR0 = OFF0 + 3 * (size_t)NN;
constexpr size_t CSR0 = CUR0 + 3 * (size_t)NN;
constexpr size_t ITOTAL = CSR0 + 3 * (size_t)EE;

__device__ int g_ibuf[ITOTAL];

// ---------------- CSR build ----------------

__global__ void zero_int_kernel(int* __restrict__ p, int n) {
    int i = blockIdx.x * blockDim.x + threadIdx.x;
    int stride = gridDim.x * blockDim.x;
    for (; i < n; i += stride) p[i] = 0;
}

__global__ void degree_kernel(const int* __restrict__ dst_ddi,
                              const int* __restrict__ dst_dpi,
                              const int* __restrict__ dst_ppi,
                              int* __restrict__ deg_ddi,
                              int* __restrict__ deg_dpi,
                              int* __restrict__ deg_ppi) {
    int i = blockIdx.x * blockDim.x + threadIdx.x;
    if (i < EE) {
        atomicAdd(&deg_ddi[dst_ddi[i]], 1);
        atomicAdd(&deg_dpi[dst_dpi[i]], 1);
        atomicAdd(&deg_ppi[dst_ppi[i]], 1);
    }
}

__global__ void __launch_bounds__(1024) scan3_kernel(int* __restrict__ ibuf) {
    const int* deg = ibuf + DEG0 + (size_t)blockIdx.x * NN;
    int* off = ibuf + OFF0 + (size_t)blockIdx.x * NN;
    int* cur = ibuf + CUR0 + (size_t)blockIdx.x * NN;

    __shared__ int warp_tot[32];
    __shared__ int carry_sh;
    int t = threadIdx.x;
    int lane = t & 31;
    int wid  = t >> 5;
    if (t == 0) carry_sh = 0;
    __syncthreads();

    for (int base = 0; base < NN; base += 1024) {
        int x = (base + t < NN) ? deg[base + t] : 0;
        int v = x;
#pragma unroll
        for (int s = 1; s < 32; s <<= 1) {
            int y = __shfl_up_sync(0xffffffffu, v, s);
            if (lane >= s) v += y;
        }
        if (lane == 31) warp_tot[wid] = v;
        __syncthreads();
        if (wid == 0) {
            int w = warp_tot[lane];
#pragma unroll
            for (int s = 1; s < 32; s <<= 1) {
                int y = __shfl_up_sync(0xffffffffu, w, s);
                if (lane >= s) w += y;
            }
            warp_tot[lane] = w;
        }
        __syncthreads();
        int warp_off = (wid == 0) ? 0 : warp_tot[wid - 1];
        int excl = v - x + warp_off;
        int c = carry_sh;
        if (base + t < NN) {
            off[base + t] = c + excl;
            cur[base + t] = c + excl;
        }
        int tile_tot = warp_tot[31];
        __syncthreads();
        if (t == 0) carry_sh = c + tile_tot;
        __syncthreads();
    }
}

__global__ void fill_csr3_kernel(const int* __restrict__ s0, const int* __restrict__ d0,
                                 int* __restrict__ c0, int* __restrict__ r0,
                                 const int* __restrict__ s1, const int* __restrict__ d1,
                                 int* __restrict__ c1, int* __restrict__ r1,
                                 const int* __restrict__ s2, const int* __restrict__ d2,
                                 int* __restrict__ c2, int* __restrict__ r2) {
    int i = blockIdx.x * blockDim.x + threadIdx.x;
    if (i < EE) {
        int p = atomicAdd(&c0[d0[i]], 1);
        r0[p] = s0[i];
    } else if (i < 2 * EE) {
        int j = i - EE;
        int p = atomicAdd(&c1[d1[j]], 1);
        r1[p] = s1[j];
    } else if (i < 3 * EE) {
        int j = i - 2 * EE;
        int p = atomicAdd(&c2[d2[j]], 1);
        r2[p] = s2[j];
    }
}

// ---------------- GEMMs: BM=64 dual fusion + register-prefetch double buffering ----

#define FMA4(accr, a, w0, w1, w2, w3)        \
    do {                                     \
        accr[0] += (a).x * (w0).x;           \
        accr[0] += (a).y * (w1).x;           \
        accr[0] += (a).z * (w2).x;           \
        accr[0] += (a).w * (w3).x;           \
        accr[1] += (a).x * (w0).y;           \
        accr[1] += (a).y * (w1).y;           \
        accr[1] += (a).z * (w2).y;           \
        accr[1] += (a).w * (w3).y;           \
        accr[2] += (a).x * (w0).z;           \
        accr[2] += (a).y * (w1).z;           \
        accr[2] += (a).z * (w2).z;           \
        accr[2] += (a).w * (w3).z;           \
        accr[3] += (a).x * (w0).w;           \
        accr[3] += (a).y * (w1).w;           \
        accr[3] += (a).z * (w2).w;           \
        accr[3] += (a).w * (w3).w;           \
    } while (0)

// single-output: C[M x N] = A[M x 128] @ W[128 x N]
template <int N, int BK>
__global__ void __launch_bounds__(256) gemm_kernel(const float* __restrict__ A,
                                                   const float* __restrict__ W,
                                                   float* __restrict__ C, int M) {
    constexpr int BM = 64;
    constexpr int K  = 128;
    constexpr int NTX = N / 4;
    constexpr int NTY = 256 / NTX;
    constexpr int TM  = BM / NTY;
    constexpr int NT  = BK * N / 4 / 256;   // float4s per thread per W tile
    constexpr int NTILES = K / BK;

    __shared__ float As[BM * K];      // 32 KB
    __shared__ float Ws[BK * N];

    int tid = threadIdx.x;
    int m0  = blockIdx.x * BM;
    int rows = M - m0; if (rows > BM) rows = BM;

    const float4* A4 = (const float4*)(A + (size_t)m0 * K);
    for (int i = tid; i < rows * (K / 4); i += 256)
        ((float4*)As)[i] = A4[i];

    int tx = tid % NTX;
    int ty = tid / NTX;
    float acc[TM][4];
#pragma unroll
    for (int r = 0; r < TM; r++) { acc[r][0]=0.f; acc[r][1]=0.f; acc[r][2]=0.f; acc[r][3]=0.f; }

    const float4* As4 = (const float4*)As;
    const float4* Ws4 = (const float4*)Ws;
    const float4* Wg  = (const float4*)W;

    // prefetch tile 0 into registers
    float4 pw[NT];
#pragma unroll
    for (int j = 0; j < NT; j++) pw[j] = Wg[tid + j * 256];

    for (int t = 0; t < NTILES; t++) {
        __syncthreads();                     // previous tile fully consumed
#pragma unroll
        for (int j = 0; j < NT; j++) ((float4*)Ws)[tid + j * 256] = pw[j];
        __syncthreads();                     // stores visible
        if (t + 1 < NTILES) {                // prefetch next tile (overlaps compute)
#pragma unroll
            for (int j = 0; j < NT; j++)
                pw[j] = Wg[(size_t)(t + 1) * (BK * N / 4) + tid + j * 256];
        }
#pragma unroll
        for (int k4 = 0; k4 < BK / 4; k4++) {
            float4 w0 = Ws4[(k4 * 4 + 0) * (N / 4) + tx];
            float4 w1 = Ws4[(k4 * 4 + 1) * (N / 4) + tx];
            float4 w2 = Ws4[(k4 * 4 + 2) * (N / 4) + tx];
            float4 w3 = Ws4[(k4 * 4 + 3) * (N / 4) + tx];
#pragma unroll
            for (int r = 0; r < TM; r++) {
                float4 a = As4[(ty * TM + r) * (K / 4) + t * (BK / 4) + k4];
                FMA4(acc[r], a, w0, w1, w2, w3);
            }
        }
    }

#pragma unroll
    for (int r = 0; r < TM; r++) {
        int m = m0 + ty * TM + r;
        if (m < M) {
            ((float4*)(C + (size_t)m * N))[tx] =
                make_float4(acc[r][0], acc[r][1], acc[r][2], acc[r][3]);
        }
    }
}

// dual-output: Ca = A@Wa, Cb = A@Wb (A tile loaded once; double-buffered W)
template <int N, int BK>
__global__ void __launch_bounds__(256) gemm_dual_kernel(const float* __restrict__ A,
                                                        const float* __restrict__ Wa,
                                                        const float* __restrict__ Wb,
                                                        float* __restrict__ Ca,
                                                        float* __restrict__ Cb, int M) {
    constexpr int BM = 64;
    constexpr int K  = 128;
    constexpr int NTX = N / 4;
    constexpr int NTY = 256 / NTX;
    constexpr int TM  = BM / NTY;
    constexpr int NT  = BK * N / 4 / 256;
    constexpr int NTILES = K / BK;

    __shared__ float As[BM * K];      // 32 KB
    __shared__ float Wsa[BK * N];     // 8 KB each
    __shared__ float Wsb[BK * N];

    int tid = threadIdx.x;
    int m0  = blockIdx.x * BM;
    int rows = M - m0; if (rows > BM) rows = BM;

    const float4* A4 = (const float4*)(A + (size_t)m0 * K);
    for (int i = tid; i < rows * (K / 4); i += 256)
        ((float4*)As)[i] = A4[i];

    int tx = tid % NTX;
    int ty = tid / NTX;
    float accA[TM][4], accB[TM][4];
#pragma unroll
    for (int r = 0; r < TM; r++) {
        accA[r][0]=0.f; accA[r][1]=0.f; accA[r][2]=0.f; accA[r][3]=0.f;
        accB[r][0]=0.f; accB[r][1]=0.f; accB[r][2]=0.f; accB[r][3]=0.f;
    }

    const float4* As4  = (const float4*)As;
    const float4* Wsa4 = (const float4*)Wsa;
    const float4* Wsb4 = (const float4*)Wsb;
    const float4* Wag  = (const float4*)Wa;
    const float4* Wbg  = (const float4*)Wb;

    float4 pa[NT], pb[NT];
#pragma unroll
    for (int j = 0; j < NT; j++) {
        pa[j] = Wag[tid + j * 256];
        pb[j] = Wbg[tid + j * 256];
    }

    for (int t = 0; t < NTILES; t++) {
        __syncthreads();
#pragma unroll
        for (int j = 0; j < NT; j++) {
            ((float4*)Wsa)[tid + j * 256] = pa[j];
            ((float4*)Wsb)[tid + j * 256] = pb[j];
        }
        __syncthreads();
        if (t + 1 < NTILES) {
#pragma unroll
            for (int j = 0; j < NT; j++) {
                pa[j] = Wag[(size_t)(t + 1) * (BK * N / 4) + tid + j * 256];
                pb[j] = Wbg[(size_t)(t + 1) * (BK * N / 4) + tid + j * 256];
            }
        }
#pragma unroll
        for (int k4 = 0; k4 < BK / 4; k4++) {
            float4 wa0 = Wsa4[(k4 * 4 + 0) * (N / 4) + tx];
            float4 wa1 = Wsa4[(k4 * 4 + 1) * (N / 4) + tx];
            float4 wa2 = Wsa4[(k4 * 4 + 2) * (N / 4) + tx];
            float4 wa3 = Wsa4[(k4 * 4 + 3) * (N / 4) + tx];
            float4 wb0 = Wsb4[(k4 * 4 + 0) * (N / 4) + tx];
            float4 wb1 = Wsb4[(k4 * 4 + 1) * (N / 4) + tx];
            float4 wb2 = Wsb4[(k4 * 4 + 2) * (N / 4) + tx];
            float4 wb3 = Wsb4[(k4 * 4 + 3) * (N / 4) + tx];
#pragma unroll
            for (int r = 0; r < TM; r++) {
                float4 a = As4[(ty * TM + r) * (K / 4) + t * (BK / 4) + k4];
                FMA4(accA[r], a, wa0, wa1, wa2, wa3);
                FMA4(accB[r], a, wb0, wb1, wb2, wb3);
            }
        }
    }

#pragma unroll
    for (int r = 0; r < TM; r++) {
        int m = m0 + ty * TM + r;
        if (m < M) {
            ((float4*)(Ca + (size_t)m * N))[tx] =
                make_float4(accA[r][0], accA[r][1], accA[r][2], accA[r][3]);
            ((float4*)(Cb + (size_t)m * N))[tx] =
                make_float4(accB[r][0], accB[r][1], accB[r][2], accB[r][3]);
        }
    }
}

// ---- gather aggregation (exact R7 versions — measured at 406us baseline) ----

__global__ void __launch_bounds__(256) agg128_kernel(const float* __restrict__ t,
                                                     const int* __restrict__ csr,
                                                     const int* __restrict__ off,
                                                     const int* __restrict__ deg,
                                                     const float* __restrict__ b,
                                                     float* __restrict__ out, int n) {
    int gw   = (blockIdx.x * blockDim.x + threadIdx.x) >> 5;
    int lane = threadIdx.x & 31;
    if (gw >= n) return;
    int o  = __ldg(&off[gw]);
    int dg = __ldg(&deg[gw]);
    int e  = o + dg;
    float4 acc = make_float4(0.f, 0.f, 0.f, 0.f);
    int i = o;
    for (; i + 3 < e; i += 4) {
        int s0 = __ldg(&csr[i]);
        int s1 = __ldg(&csr[i + 1]);
        int s2 = __ldg(&csr[i + 2]);
        int s3 = __ldg(&csr[i + 3]);
        float4 v0 = __ldg((const float4*)(t + (size_t)s0 * 128) + lane);
        float4 v1 = __ldg((const float4*)(t + (size_t)s1 * 128) + lane);
        float4 v2 = __ldg((const float4*)(t + (size_t)s2 * 128) + lane);
        float4 v3 = __ldg((const float4*)(t + (size_t)s3 * 128) + lane);
        acc.x += (v0.x + v1.x) + (v2.x + v3.x);
        acc.y += (v0.y + v1.y) + (v2.y + v3.y);
        acc.z += (v0.z + v1.z) + (v2.z + v3.z);
        acc.w += (v0.w + v1.w) + (v2.w + v3.w);
    }
    for (; i < e; i++) {
        int s = __ldg(&csr[i]);
        float4 v = __ldg((const float4*)(t + (size_t)s * 128) + lane);
        acc.x += v.x; acc.y += v.y; acc.z += v.z; acc.w += v.w;
    }
    float inv = 1.0f / fmaxf((float)dg, 1.0f);
    float4 bb = __ldg((const float4*)b + lane);
    ((float4*)(out + (size_t)gw * 128))[lane] =
        make_float4(acc.x * inv + bb.x, acc.y * inv + bb.y,
                    acc.z * inv + bb.z, acc.w * inv + bb.w);
}

__global__ void __launch_bounds__(256) agg128_dual_kernel(
        const float* __restrict__ tA, const int* __restrict__ csrA,
        const int* __restrict__ offA, const int* __restrict__ degA,
        const float* __restrict__ bA,
        const float* __restrict__ tB, const int* __restrict__ csrB,
        const int* __restrict__ offB, const int* __restrict__ degB,
        const float* __restrict__ bB,
        float* __restrict__ out, int n) {
    int gw   = (blockIdx.x * blockDim.x + threadIdx.x) >> 5;
    int lane = threadIdx.x & 31;
    if (gw >= n) return;

    int dgA = __ldg(&degA[gw]);
    int dgB = __ldg(&degB[gw]);

    float4 accA = make_float4(0.f, 0.f, 0.f, 0.f);
    {
        int o = __ldg(&offA[gw]); int e = o + dgA;
        int i = o;
        for (; i + 3 < e; i += 4) {
            int s0 = __ldg(&csrA[i]);
            int s1 = __ldg(&csrA[i + 1]);
            int s2 = __ldg(&csrA[i + 2]);
            int s3 = __ldg(&csrA[i + 3]);
            float4 v0 = __ldg((const float4*)(tA + (size_t)s0 * 128) + lane);
            float4 v1 = __ldg((const float4*)(tA + (size_t)s1 * 128) + lane);
            float4 v2 = __ldg((const float4*)(tA + (size_t)s2 * 128) + lane);
            float4 v3 = __ldg((const float4*)(tA + (size_t)s3 * 128) + lane);
            accA.x += (v0.x + v1.x) + (v2.x + v3.x);
            accA.y += (v0.y + v1.y) + (v2.y + v3.y);
            accA.z += (v0.z + v1.z) + (v2.z + v3.z);
            accA.w += (v0.w + v1.w) + (v2.w + v3.w);
        }
        for (; i < e; i++) {
            int s = __ldg(&csrA[i]);
            float4 v = __ldg((const float4*)(tA + (size_t)s * 128) + lane);
            accA.x += v.x; accA.y += v.y; accA.z += v.z; accA.w += v.w;
        }
    }
    float4 accB = make_float4(0.f, 0.f, 0.f, 0.f);
    {
        int o = __ldg(&offB[gw]); int e = o + dgB;
        int i = o;
        for (; i + 3 < e; i += 4) {
            int s0 = __ldg(&csrB[i]);
            int s1 = __ldg(&csrB[i + 1]);
            int s2 = __ldg(&csrB[i + 2]);
            int s3 = __ldg(&csrB[i + 3]);
            float4 v0 = __ldg((const float4*)(tB + (size_t)s0 * 128) + lane);
            float4 v1 = __ldg((const float4*)(tB + (size_t)s1 * 128) + lane);
            float4 v2 = __ldg((const float4*)(tB + (size_t)s2 * 128) + lane);
            float4 v3 = __ldg((const float4*)(tB + (size_t)s3 * 128) + lane);
            accB.x += (v0.x + v1.x) + (v2.x + v3.x);
            accB.y += (v0.y + v1.y) + (v2.y + v3.y);
            accB.z += (v0.z + v1.z) + (v2.z + v3.z);
            accB.w += (v0.w + v1.w) + (v2.w + v3.w);
        }
        for (; i < e; i++) {
            int s = __ldg(&csrB[i]);
            float4 v = __ldg((const float4*)(tB + (size_t)s * 128) + lane);
            accB.x += v.x; accB.y += v.y; accB.z += v.z; accB.w += v.w;
        }
    }
    float invA = 1.0f / fmaxf((float)dgA, 1.0f);
    float invB = 1.0f / fmaxf((float)dgB, 1.0f);
    float4 bbA = __ldg((const float4*)bA + lane);
    float4 bbB = __ldg((const float4*)bB + lane);
    ((float4*)(out + (size_t)gw * 128))[lane] =
        make_float4(accA.x * invA + bbA.x + accB.x * invB + bbB.x,
                    accA.y * invA + bbA.y + accB.y * invB + bbB.y,
                    accA.z * invA + bbA.z + accB.z * invB + bbB.z,
                    accA.w * invA + bbA.w + accB.w * invB + bbB.w);
}

__global__ void __launch_bounds__(256) agg64_kernel(const float* __restrict__ t,
                                                    const int* __restrict__ csr,
                                                    const int* __restrict__ off,
                                                    const int* __restrict__ deg,
                                                    const float* __restrict__ b,
                                                    float* __restrict__ out, int n) {
    int gw   = (blockIdx.x * blockDim.x + threadIdx.x) >> 5;
    int lane = threadIdx.x & 31;
    if (gw >= n) return;
    int half = lane >> 4;
    int sub  = lane & 15;
    int o  = __ldg(&off[gw]);
    int dg = __ldg(&deg[gw]);
    int e  = o + dg;
    float4 acc = make_float4(0.f, 0.f, 0.f, 0.f);
    int i = o;
    for (; i + 3 < e; i += 4) {
        int s0 = __ldg(&csr[i + half]);
        int s1 = __ldg(&csr[i + 2 + half]);
        float4 v0 = __ldg((const float4*)(t + (size_t)s0 * 64) + sub);
        float4 v1 = __ldg((const float4*)(t + (size_t)s1 * 64) + sub);
        acc.x += v0.x + v1.x; acc.y += v0.y + v1.y;
        acc.z += v0.z + v1.z; acc.w += v0.w + v1.w;
    }
    for (; i + 1 < e; i += 2) {
        int s = __ldg(&csr[i + half]);
        float4 v = __ldg((const float4*)(t + (size_t)s * 64) + sub);
        acc.x += v.x; acc.y += v.y; acc.z += v.z; acc.w += v.w;
    }
    if (i < e && half == 0) {
        int s = __ldg(&csr[i]);
        float4 v = __ldg((const float4*)(t + (size_t)s * 64) + sub);
        acc.x += v.x; acc.y += v.y; acc.z += v.z; acc.w += v.w;
    }
    acc.x += __shfl_xor_sync(0xffffffffu, acc.x, 16);
    acc.y += __shfl_xor_sync(0xffffffffu, acc.y, 16);
    acc.z += __shfl_xor_sync(0xffffffffu, acc.z, 16);
    acc.w += __shfl_xor_sync(0xffffffffu, acc.w, 16);
    if (half == 0) {
        float inv = 1.0f / fmaxf((float)dg, 1.0f);
        float4 bb = __ldg((const float4*)b + sub);
        ((float4*)(out + (size_t)gw * 64))[sub] =
            make_float4(acc.x * inv + bb.x, acc.y * inv + bb.y,
                        acc.z * inv + bb.z, acc.w * inv + bb.w);
    }
}

__global__ void __launch_bounds__(256) agg64_dual_kernel(
        const float* __restrict__ tA, const int* __restrict__ csrA,
        const int* __restrict__ offA, const int* __restrict__ degA,
        const float* __restrict__ bA,
        const float* __restrict__ tB, const int* __restrict__ csrB,
        const int* __restrict__ offB, const int* __restrict__ degB,
        const float* __restrict__ bB,
        float* __restrict__ out, int n) {
    int gw   = (blockIdx.x * blockDim.x + threadIdx.x) >> 5;
    int lane = threadIdx.x & 31;
    if (gw >= n) return;
    int half = lane >> 4;
    int sub  = lane & 15;

    int dgA = __ldg(&degA[gw]);
    int dgB = __ldg(&degB[gw]);

    float4 accA = make_float4(0.f, 0.f, 0.f, 0.f);
    {
        int o = __ldg(&offA[gw]); int e = o + dgA;
        int i = o;
        for (; i + 3 < e; i += 4) {
            int s0 = __ldg(&csrA[i + half]);
            int s1 = __ldg(&csrA[i + 2 + half]);
            float4 v0 = __ldg((const float4*)(tA + (size_t)s0 * 64) + sub);
            float4 v1 = __ldg((const float4*)(tA + (size_t)s1 * 64) + sub);
            accA.x += v0.x + v1.x; accA.y += v0.y + v1.y;
            accA.z += v0.z + v1.z; accA.w += v0.w + v1.w;
        }
        for (; i + 1 < e; i += 2) {
            int s = __ldg(&csrA[i + half]);
            float4 v = __ldg((const float4*)(tA + (size_t)s * 64) + sub);
            accA.x += v.x; accA.y += v.y; accA.z += v.z; accA.w += v.w;
        }
        if (i < e && half == 0) {
            int s = __ldg(&csrA[i]);
            float4 v = __ldg((const float4*)(tA + (size_t)s * 64) + sub);
            accA.x += v.x; accA.y += v.y; accA.z += v.z; accA.w += v.w;
        }
    }
    float4 accB = make_float4(0.f, 0.f, 0.f, 0.f);
    {
        int o = __ldg(&offB[gw]); int e = o + dgB;
        int i = o;
        for (; i + 3 < e; i += 4) {
            int s0 = __ldg(&csrB[i + half]);
            int s1 = __ldg(&csrB[i + 2 + half]);
            float4 v0 = __ldg((const float4*)(tB + (size_t)s0 * 64) + sub);
            float4 v1 = __ldg((const float4*)(tB + (size_t)s1 * 64) + sub);
            accB.x += v0.x + v1.x; accB.y += v0.y + v1.y;
            accB.z += v0.z + v1.z; accB.w += v0.w + v1.w;
        }
        for (; i + 1 < e; i += 2) {
            int s = __ldg(&csrB[i + half]);
            float4 v = __ldg((const float4*)(tB + (size_t)s * 64) + sub);
            accB.x += v.x; accB.y += v.y; accB.z += v.z; accB.w += v.w;
        }
        if (i < e && half == 0) {
            int s = __ldg(&csrB[i]);
            float4 v = __ldg((const float4*)(tB + (size_t)s * 64) + sub);
            accB.x += v.x; accB.y += v.y; accB.z += v.z; accB.w += v.w;
        }
    }
    accA.x += __shfl_xor_sync(0xffffffffu, accA.x, 16);
    accA.y += __shfl_xor_sync(0xffffffffu, accA.y, 16);
    accA.z += __shfl_xor_sync(0xffffffffu, accA.z, 16);
    accA.w += __shfl_xor_sync(0xffffffffu, accA.w, 16);
    accB.x += __shfl_xor_sync(0xffffffffu, accB.x, 16);
    accB.y += __shfl_xor_sync(0xffffffffu, accB.y, 16);
    accB.z += __shfl_xor_sync(0xffffffffu, accB.z, 16);
    accB.w += __shfl_xor_sync(0xffffffffu, accB.w, 16);
    if (half == 0) {
        float invA = 1.0f / fmaxf((float)dgA, 1.0f);
        float invB = 1.0f / fmaxf((float)dgB, 1.0f);
        float4 bbA = __ldg((const float4*)bA + sub);
        float4 bbB = __ldg((const float4*)bB + sub);
        ((float4*)(out + (size_t)gw * 64))[sub] =
            make_float4(accA.x * invA + bbA.x + accB.x * invB + bbB.x,
                        accA.y * invA + bbA.y + accB.y * invB + bbB.y,
                        accA.z * invA + bbA.z + accB.z * invB + bbB.z,
                        accA.w * invA + bbA.w + accB.w * invB + bbB.w);
    }
}

// ---------------- launch ----------------

extern "C" void kernel_launch(void* const* d_in, const int* in_sizes, int n_in,
                              void* d_out, int out_size) {
    const float* x_drug = (const float*)d_in[0];
    const float* x_prot = (const float*)d_in[1];
    const int* src_ddi  = (const int*)d_in[2];
    const int* dst_ddi  = (const int*)d_in[3];
    const int* src_dpi  = (const int*)d_in[4];
    const int* dst_dpi  = (const int*)d_in[5];
    const int* src_ppi  = (const int*)d_in[6];
    const int* dst_ppi  = (const int*)d_in[7];
    const float* W1_ddi = (const float*)d_in[8];
    const float* b1_ddi = (const float*)d_in[9];
    const float* W1_dpi = (const float*)d_in[10];
    const float* b1_dpi = (const float*)d_in[11];
    const float* W1_ppi = (const float*)d_in[12];
    const float* b1_ppi = (const float*)d_in[13];
    const float* W2_ddi = (const float*)d_in[14];
    const float* b2_ddi = (const float*)d_in[15];
    const float* W2_dpi = (const float*)d_in[16];
    const float* b2_dpi = (const float*)d_in[17];
    const float* W2_ppi = (const float*)d_in[18];
    const float* b2_ppi = (const float*)d_in[19];
    float* out = (float*)d_out;

    float* B = nullptr;
    cudaGetSymbolAddress((void**)&B, g_buf);
    int* IB = nullptr;
    cudaGetSymbolAddress((void**)&IB, g_ibuf);

    float* h_d    = B + H_D;
    float* h_p    = B + H_P;
    float* t1_ddi = B + T1_DDI;
    float* t1_dpi = B + T1_DPI;
    float* t1_ppi = B + T1_PPI;
    float* t2_ddi = B + T2_DDI;
    float* t2_dpi = B + T2_DPI;
    float* t2_ppi = B + T2_PPI;

    int* deg_ddi = IB + DEG0;
    int* deg_dpi = IB + DEG0 + NN;
    int* deg_ppi = IB + DEG0 + 2 * NN;
    int* off_ddi = IB + OFF0;
    int* off_dpi = IB + OFF0 + NN;
    int* off_ppi = IB + OFF0 + 2 * NN;
    int* cur_ddi = IB + CUR0;
    int* cur_dpi = IB + CUR0 + NN;
    int* cur_ppi = IB + CUR0 + 2 * NN;
    int* csr_ddi = IB + CSR0;
    int* csr_dpi = IB + CSR0 + EE;
    int* csr_ppi = IB + CSR0 + 2 * EE;

    // ---- build CSR (3 relations) ----
    zero_int_kernel<<<64, 1024>>>(IB + DEG0, 3 * NN);
    degree_kernel<<<(EE + 255) / 256, 256>>>(dst_ddi, dst_dpi, dst_ppi,
                                             deg_ddi, deg_dpi, deg_ppi);
    scan3_kernel<<<3, 1024>>>(IB);
    fill_csr3_kernel<<<(3 * EE + 255) / 256, 256>>>(
        src_ddi, dst_ddi, cur_ddi, csr_ddi,
        src_dpi, dst_dpi, cur_dpi, csr_dpi,
        src_ppi, dst_ppi, cur_ppi, csr_ppi);

    // ---- layer 1 ----
    const int GB = (NN + 63) / 64;
    gemm_dual_kernel<128, 16><<<GB, 256>>>(x_drug, W1_ddi, W1_dpi, t1_ddi, t1_dpi, ND);
    gemm_kernel<128, 32><<<GB, 256>>>(x_prot, W1_ppi, t1_ppi, NP);

    const int AB = (NN * 32 + 255) / 256;
    agg128_kernel<<<AB, 256>>>(t1_ddi, csr_ddi, off_ddi, deg_ddi, b1_ddi, h_d, ND);
    agg128_dual_kernel<<<AB, 256>>>(t1_dpi, csr_dpi, off_dpi, deg_dpi, b1_dpi,
                                    t1_ppi, csr_ppi, off_ppi, deg_ppi, b1_ppi,
                                    h_p, NP);

    // ---- layer 2 ----
    gemm_dual_kernel<64, 32><<<GB, 256>>>(h_d, W2_ddi, W2_dpi, t2_ddi, t2_dpi, ND);
    gemm_kernel<64, 32><<<GB, 256>>>(h_p, W2_ppi, t2_ppi, NP);

    agg64_kernel<<<AB, 256>>>(t2_ddi, csr_ddi, off_ddi, deg_ddi, b2_ddi, out, ND);
    agg64_dual_kernel<<<AB, 256>>>(t2_dpi, csr_dpi, off_dpi, deg_dpi, b2_dpi,
                                   t2_ppi, csr_ppi, off_ppi, deg_ppi, b2_ppi,
                                   out + (size_t)ND * DO, NP);
}